// round 1
// baseline (speedup 1.0000x reference)
#include <cuda_runtime.h>
#include <math.h>

#define B_  64
#define T_  256
#define D_  1024
#define H_  1024
#define G4  4096   // 4*H

// ---- scratch (device globals: no allocation allowed) ----
__device__ float g_gx[(size_t)T_ * B_ * G4];     // [T][B][4H]  256 MB
__device__ float g_hs[(size_t)B_ * T_ * H_];     // [B][T][H]    64 MB
__device__ float g_hbuf[2][B_ * H_];             // h ping-pong
__device__ float g_cbuf[B_ * H_];                // c (in-place safe: 1 owner/elem)

// ============================================================
// SGEMM 128x128x8, 8x8 microtile, 256 threads.
// Per call: M = 16384 (grid.y=128), N = 1024 (grid.x=8), K = 1024, ldb = 1024.
// REMAP=true: A rows are (b*T+t) from x[B,T,D]; C row goes to (t*B+b)*ldc (gx layout).
// ============================================================
template<bool REMAP>
__global__ __launch_bounds__(256) void sgemm128(
    const float* __restrict__ A, const float* __restrict__ Bm,
    const float* __restrict__ bias, float* __restrict__ C, int ldc)
{
    const int K = 1024;
    __shared__ float As[8][128];   // [k][m] (transposed)
    __shared__ float Bs[8][128];   // [k][n]

    int tid = threadIdx.x;
    int tx  = tid & 15;            // 0..15 -> 8 cols each
    int ty  = tid >> 4;            // 0..15 -> 8 rows each
    int m0  = blockIdx.y * 128;
    int n0  = blockIdx.x * 128;

    float acc[8][8] = {};

    int a_row  = tid >> 1;         // 0..127
    int a_col4 = (tid & 1) * 4;    // 0 or 4
    int b_row  = tid >> 5;         // 0..7
    int b_col4 = (tid & 31) * 4;   // 0..124

    const float* Ag = A  + (size_t)(m0 + a_row) * K + a_col4;
    const float* Bg = Bm + (size_t)b_row * 1024 + n0 + b_col4;

    for (int k0 = 0; k0 < K; k0 += 8) {
        float4 av = *(const float4*)(Ag + k0);
        float4 bv = *(const float4*)(Bg + (size_t)k0 * 1024);
        __syncthreads();
        As[a_col4 + 0][a_row] = av.x;
        As[a_col4 + 1][a_row] = av.y;
        As[a_col4 + 2][a_row] = av.z;
        As[a_col4 + 3][a_row] = av.w;
        *(float4*)&Bs[b_row][b_col4] = bv;
        __syncthreads();

        #pragma unroll
        for (int kk = 0; kk < 8; kk++) {
            float af[8], bf[8];
            *(float4*)(af)     = *(const float4*)&As[kk][ty * 8];
            *(float4*)(af + 4) = *(const float4*)&As[kk][ty * 8 + 4];
            *(float4*)(bf)     = *(const float4*)&Bs[kk][tx * 8];
            *(float4*)(bf + 4) = *(const float4*)&Bs[kk][tx * 8 + 4];
            #pragma unroll
            for (int i = 0; i < 8; i++)
                #pragma unroll
                for (int j = 0; j < 8; j++)
                    acc[i][j] += af[i] * bf[j];
        }
    }

    #pragma unroll
    for (int i = 0; i < 8; i++) {
        int r = m0 + ty * 8 + i;
        size_t rowoff;
        if (REMAP) {
            // r = b*T + t  ->  row (t*B + b) of gx
            int b = r >> 8;          // /T_ (T_=256)
            int t = r & 255;
            rowoff = ((size_t)t * B_ + b) * (size_t)ldc;
        } else {
            rowoff = (size_t)r * (size_t)ldc;
        }
        #pragma unroll
        for (int j = 0; j < 8; j += 4) {
            int col = n0 + tx * 8 + j;
            float4 v;
            v.x = acc[i][j + 0] + bias[col + 0];
            v.y = acc[i][j + 1] + bias[col + 1];
            v.z = acc[i][j + 2] + bias[col + 2];
            v.w = acc[i][j + 3] + bias[col + 3];
            *(float4*)(C + rowoff + col) = v;
        }
    }
}

// ============================================================
// One recurrence step. Grid = 128 blocks (H/8), 256 threads.
// Block handles 8 h-columns for ALL 4 gates and all 64 batch rows,
// so gates combine in-register (no temp g buffer, one kernel/step).
// warp w (tid>>5) owns column n0+w; lane owns rows lane, lane+32.
// ============================================================
__global__ __launch_bounds__(256) void lstm_step(
    const float* __restrict__ Ui, const float* __restrict__ Uf,
    const float* __restrict__ Uj, const float* __restrict__ Uo, int t)
{
    __shared__ float sh[64][9];      // h tile [row][k], padded (stride 9: conflict-free)
    __shared__ float su[4][8][8];    // U tile [gate][k][col]

    int tid  = threadIdx.x;
    int w    = tid >> 5;             // 0..7: column within tile
    int lane = tid & 31;
    int n0   = blockIdx.x * 8;

    const float* hprev = g_hbuf[t & 1];

    // U loader role: 4 gates x 8 k x 8 cols = 256 elems, one per thread
    int ug  = tid >> 6;              // gate 0..3
    int rem = tid & 63;
    int ukk = rem >> 3, uc = rem & 7;
    const float* Up = (ug == 0) ? Ui : (ug == 1) ? Uf : (ug == 2) ? Uj : Uo;
    const float* Uload = Up + n0 + uc;

    // h loader role: 64 rows x 8 k = 512 elems, float2 per thread
    int idx0 = tid * 2;
    int hr = idx0 >> 3, hk = idx0 & 7;   // hk even -> float2 within row

    float acc[4][2] = {};

    for (int k0 = 0; k0 < 1024; k0 += 8) {
        float2 hv = *(const float2*)(hprev + hr * 1024 + k0 + hk);
        float  uv = Uload[(size_t)(k0 + ukk) * 1024];
        __syncthreads();
        sh[hr][hk]     = hv.x;
        sh[hr][hk + 1] = hv.y;
        su[ug][ukk][uc] = uv;
        __syncthreads();

        #pragma unroll
        for (int kk = 0; kk < 8; kk++) {
            float a0 = sh[lane][kk];
            float a1 = sh[lane + 32][kk];
            float vi = su[0][kk][w];
            float vf = su[1][kk][w];
            float vj = su[2][kk][w];
            float vo = su[3][kk][w];
            acc[0][0] += a0 * vi;  acc[0][1] += a1 * vi;
            acc[1][0] += a0 * vf;  acc[1][1] += a1 * vf;
            acc[2][0] += a0 * vj;  acc[2][1] += a1 * vj;
            acc[3][0] += a0 * vo;  acc[3][1] += a1 * vo;
        }
    }

    const float* gxr = g_gx + (size_t)t * B_ * G4;
    float* hnext = g_hbuf[(t + 1) & 1];
    int n = n0 + w;

    #pragma unroll
    for (int p = 0; p < 2; p++) {
        int b = lane + p * 32;
        float gi = acc[0][p] + gxr[(size_t)b * G4 + n];
        float gf = acc[1][p] + gxr[(size_t)b * G4 + 1024 + n];
        float gj = acc[2][p] + gxr[(size_t)b * G4 + 2048 + n];
        float go = acc[3][p] + gxr[(size_t)b * G4 + 3072 + n];
        float iv = 1.f / (1.f + expf(-gi));
        float fv = 1.f / (1.f + expf(-gf));
        float jv = tanhf(gj);
        float ov = 1.f / (1.f + expf(-go));
        float c  = fv * g_cbuf[b * H_ + n] + iv * jv;
        g_cbuf[b * H_ + n] = c;
        float h = ov * tanhf(c);
        hnext[b * H_ + n] = h;
        g_hs[(size_t)b * T_ * H_ + (size_t)t * H_ + n] = h;
    }
}

// ============================================================
// Inputs (metadata order): x, h0, c0, W_i, W_f, W_j, W_o,
//   U_i, U_f, U_j, U_o, b_i, b_f, b_j, b_o, W_y, b_y
// ============================================================
extern "C" void kernel_launch(void* const* d_in, const int* in_sizes, int n_in,
                              void* d_out, int out_size)
{
    const float* x  = (const float*)d_in[0];
    const float* h0 = (const float*)d_in[1];
    const float* c0 = (const float*)d_in[2];
    const float* W[4] = {(const float*)d_in[3], (const float*)d_in[4],
                         (const float*)d_in[5], (const float*)d_in[6]};
    const float* U[4] = {(const float*)d_in[7], (const float*)d_in[8],
                         (const float*)d_in[9], (const float*)d_in[10]};
    const float* bb[4] = {(const float*)d_in[11], (const float*)d_in[12],
                          (const float*)d_in[13], (const float*)d_in[14]};
    const float* Wy = (const float*)d_in[15];
    const float* by = (const float*)d_in[16];
    float* y = (float*)d_out;

    // seed h, c
    cudaMemcpyToSymbolAsync(g_hbuf, h0, (size_t)B_ * H_ * sizeof(float), 0,
                            cudaMemcpyDeviceToDevice, 0);
    cudaMemcpyToSymbolAsync(g_cbuf, c0, (size_t)B_ * H_ * sizeof(float), 0,
                            cudaMemcpyDeviceToDevice, 0);

    float* gx_ptr; cudaGetSymbolAddress((void**)&gx_ptr, g_gx);
    float* hs_ptr; cudaGetSymbolAddress((void**)&hs_ptr, g_hs);

    dim3 grid(8, 128);  // N=1024, M=16384

    // gx = x @ [W_i|W_f|W_j|W_o] + b   (one call per gate, column band of gx)
    for (int g = 0; g < 4; g++)
        sgemm128<true><<<grid, 256>>>(x, W[g], bb[g], gx_ptr + g * 1024, G4);

    // sequential recurrence
    for (int t = 0; t < T_; t++)
        lstm_step<<<128, 256>>>(U[0], U[1], U[2], U[3], t);

    // y = hs @ W_y + b_y
    sgemm128<false><<<grid, 256>>>(hs_ptr, Wy, by, y, 1024);
}

// round 2
// speedup vs baseline: 1.7731x; 1.7731x over previous
#include <cuda_runtime.h>
#include <math.h>

#define B_  64
#define T_  256
#define D_  1024
#define H_  1024
#define G4  4096   // 4*H
#define NBLK 128   // persistent grid (<=148, 1 block/SM at this smem size)
#define KC  128    // h chunk along K
#define HPAD 132   // padded row stride for h smem chunk (16B-aligned, bank-spread)

// ---- scratch (device globals: no allocation allowed) ----
__device__ float g_gx[(size_t)T_ * B_ * G4];     // [T][B][4H]  256 MB
__device__ float g_hs[(size_t)B_ * T_ * H_];     // [B][T][H]    64 MB
__device__ float g_hbuf[2][B_ * H_];             // h ping-pong
__device__ float g_cbuf[B_ * H_];                // c state

// grid barrier state (count self-resets each barrier; gen is monotonic)
__device__ unsigned g_bar_count = 0;
__device__ unsigned g_bar_gen   = 0;

// ============================================================
// SGEMM 128x128x8, 8x8 microtile, 256 threads (unchanged from R1).
// ============================================================
template<bool REMAP>
__global__ __launch_bounds__(256) void sgemm128(
    const float* __restrict__ A, const float* __restrict__ Bm,
    const float* __restrict__ bias, float* __restrict__ C, int ldc)
{
    const int K = 1024;
    __shared__ float As[8][128];
    __shared__ float Bs[8][128];

    int tid = threadIdx.x;
    int tx  = tid & 15;
    int ty  = tid >> 4;
    int m0  = blockIdx.y * 128;
    int n0  = blockIdx.x * 128;

    float acc[8][8] = {};

    int a_row  = tid >> 1;
    int a_col4 = (tid & 1) * 4;
    int b_row  = tid >> 5;
    int b_col4 = (tid & 31) * 4;

    const float* Ag = A  + (size_t)(m0 + a_row) * K + a_col4;
    const float* Bg = Bm + (size_t)b_row * 1024 + n0 + b_col4;

    for (int k0 = 0; k0 < K; k0 += 8) {
        float4 av = *(const float4*)(Ag + k0);
        float4 bv = *(const float4*)(Bg + (size_t)k0 * 1024);
        __syncthreads();
        As[a_col4 + 0][a_row] = av.x;
        As[a_col4 + 1][a_row] = av.y;
        As[a_col4 + 2][a_row] = av.z;
        As[a_col4 + 3][a_row] = av.w;
        *(float4*)&Bs[b_row][b_col4] = bv;
        __syncthreads();

        #pragma unroll
        for (int kk = 0; kk < 8; kk++) {
            float af[8], bf[8];
            *(float4*)(af)     = *(const float4*)&As[kk][ty * 8];
            *(float4*)(af + 4) = *(const float4*)&As[kk][ty * 8 + 4];
            *(float4*)(bf)     = *(const float4*)&Bs[kk][tx * 8];
            *(float4*)(bf + 4) = *(const float4*)&Bs[kk][tx * 8 + 4];
            #pragma unroll
            for (int i = 0; i < 8; i++)
                #pragma unroll
                for (int j = 0; j < 8; j++)
                    acc[i][j] += af[i] * bf[j];
        }
    }

    #pragma unroll
    for (int i = 0; i < 8; i++) {
        int r = m0 + ty * 8 + i;
        size_t rowoff;
        if (REMAP) {
            int b = r >> 8;
            int t = r & 255;
            rowoff = ((size_t)t * B_ + b) * (size_t)ldc;
        } else {
            rowoff = (size_t)r * (size_t)ldc;
        }
        #pragma unroll
        for (int j = 0; j < 8; j += 4) {
            int col = n0 + tx * 8 + j;
            float4 v;
            v.x = acc[i][j + 0] + bias[col + 0];
            v.y = acc[i][j + 1] + bias[col + 1];
            v.z = acc[i][j + 2] + bias[col + 2];
            v.w = acc[i][j + 3] + bias[col + 3];
            *(float4*)(C + rowoff + col) = v;
        }
    }
}

// ============================================================
// Persistent LSTM recurrence. Grid = 128 blocks x 256 threads.
// Block bn owns h-columns n0 = bn*8 .. +8 for all 4 gates.
// U slice (4 x 1024 x 8 = 128 KB) staged in smem ONCE for all 256 steps.
// h double-buffered through smem in 128-k chunks with register prefetch.
// Grid-wide spin barrier per step (all blocks co-resident).
// ============================================================
__device__ __forceinline__ void grid_sync_128(int tid)
{
    __syncthreads();
    if (tid == 0) {
        unsigned gen = *(volatile unsigned*)&g_bar_gen;
        __threadfence();
        if (atomicAdd(&g_bar_count, 1u) == NBLK - 1) {
            g_bar_count = 0;
            __threadfence();
            atomicExch(&g_bar_gen, gen + 1u);
        } else {
            while (*(volatile unsigned*)&g_bar_gen == gen) { __nanosleep(64); }
            __threadfence();
        }
    }
    __syncthreads();
}

extern "C" __global__ void __launch_bounds__(256, 1) lstm_persistent(
    const float* __restrict__ Ui, const float* __restrict__ Uf,
    const float* __restrict__ Uj, const float* __restrict__ Uo)
{
    extern __shared__ float smem[];
    float* su = smem;                    // [4][1024][8]  = 32768 floats
    float* sh = smem + 4 * 1024 * 8;     // [2][64][HPAD] = 2*64*132 floats

    const int tid = threadIdx.x;
    const int n0  = blockIdx.x * 8;
    const int cn  = tid & 7;             // column within the 8-col slice
    const int r0  = (tid >> 3) * 2;      // row pair (0..62 even)

    // ---- stage U once: su[g][k][c] = U_g[k*1024 + n0 + c] ----
    const float* Uptr[4] = {Ui, Uf, Uj, Uo};
    for (int i = 0; i < 128; i++) {
        int idx = i * 256 + tid;         // 0..32767
        int g   = idx >> 13;
        int k   = (idx >> 3) & 1023;
        int c   = idx & 7;
        su[idx] = Uptr[g][(size_t)k * 1024 + n0 + c];
    }
    __syncthreads();

    for (int t = 0; t < T_; t++) {
        const float* hprev = g_hbuf[t & 1];
        float*       hnext = g_hbuf[(t + 1) & 1];

        float acc[4][2] = {};

        // prefetch chunk 0 (8 float4 per thread) and store to buf 0
        float4 pf[8];
        #pragma unroll
        for (int i = 0; i < 8; i++) {
            int f4  = i * 256 + tid;     // 0..2047
            int row = f4 >> 5;
            int kq  = f4 & 31;
            pf[i] = *(const float4*)(hprev + (size_t)row * H_ + kq * 4);
        }
        #pragma unroll
        for (int i = 0; i < 8; i++) {
            int f4  = i * 256 + tid;
            int row = f4 >> 5;
            int kq  = f4 & 31;
            *(float4*)(sh + row * HPAD + kq * 4) = pf[i];
        }

        for (int cch = 0; cch < 8; cch++) {
            if (cch < 7) {
                int k0 = (cch + 1) * KC;
                #pragma unroll
                for (int i = 0; i < 8; i++) {
                    int f4  = i * 256 + tid;
                    int row = f4 >> 5;
                    int kq  = f4 & 31;
                    pf[i] = *(const float4*)(hprev + (size_t)row * H_ + k0 + kq * 4);
                }
            }
            __syncthreads();   // buf[cch&1] ready; prior compute done
            if (cch < 7) {
                float* dst = sh + ((cch + 1) & 1) * (64 * HPAD);
                #pragma unroll
                for (int i = 0; i < 8; i++) {
                    int f4  = i * 256 + tid;
                    int row = f4 >> 5;
                    int kq  = f4 & 31;
                    *(float4*)(dst + row * HPAD + kq * 4) = pf[i];
                }
            }

            const float* shb = sh + (cch & 1) * (64 * HPAD);
            const float* ub  = su + (size_t)cch * KC * 8 + cn;
            #pragma unroll 8
            for (int kk = 0; kk < KC; kk++) {
                float a0 = shb[r0 * HPAD + kk];
                float a1 = shb[(r0 + 1) * HPAD + kk];
                const float* up = ub + kk * 8;
                float vi = up[0];
                float vf = up[8192];
                float vj = up[16384];
                float vo = up[24576];
                acc[0][0] += a0 * vi;  acc[0][1] += a1 * vi;
                acc[1][0] += a0 * vf;  acc[1][1] += a1 * vf;
                acc[2][0] += a0 * vj;  acc[2][1] += a1 * vj;
                acc[3][0] += a0 * vo;  acc[3][1] += a1 * vo;
            }
        }

        // epilogue: gates + state update for (rows r0, r0+1) x col n0+cn
        const float* gxr = g_gx + (size_t)t * B_ * G4;
        int n = n0 + cn;
        #pragma unroll
        for (int p = 0; p < 2; p++) {
            int b = r0 + p;
            float gi = acc[0][p] + gxr[(size_t)b * G4 + n];
            float gf = acc[1][p] + gxr[(size_t)b * G4 + 1024 + n];
            float gj = acc[2][p] + gxr[(size_t)b * G4 + 2048 + n];
            float go = acc[3][p] + gxr[(size_t)b * G4 + 3072 + n];
            float iv = 1.f / (1.f + expf(-gi));
            float fv = 1.f / (1.f + expf(-gf));
            float jv = tanhf(gj);
            float ov = 1.f / (1.f + expf(-go));
            float c  = fv * g_cbuf[b * H_ + n] + iv * jv;
            g_cbuf[b * H_ + n] = c;
            float h = ov * tanhf(c);
            hnext[b * H_ + n] = h;
            g_hs[(size_t)b * T_ * H_ + (size_t)t * H_ + n] = h;
        }

        grid_sync_128(tid);
    }
}

// ============================================================
// Inputs: x, h0, c0, W_i..W_o, U_i..U_o, b_i..b_o, W_y, b_y
// ============================================================
extern "C" void kernel_launch(void* const* d_in, const int* in_sizes, int n_in,
                              void* d_out, int out_size)
{
    const float* x  = (const float*)d_in[0];
    const float* h0 = (const float*)d_in[1];
    const float* c0 = (const float*)d_in[2];
    const float* W[4] = {(const float*)d_in[3], (const float*)d_in[4],
                         (const float*)d_in[5], (const float*)d_in[6]};
    const float* U[4] = {(const float*)d_in[7], (const float*)d_in[8],
                         (const float*)d_in[9], (const float*)d_in[10]};
    const float* bb[4] = {(const float*)d_in[11], (const float*)d_in[12],
                          (const float*)d_in[13], (const float*)d_in[14]};
    const float* Wy = (const float*)d_in[15];
    const float* by = (const float*)d_in[16];
    float* y = (float*)d_out;

    cudaMemcpyToSymbolAsync(g_hbuf, h0, (size_t)B_ * H_ * sizeof(float), 0,
                            cudaMemcpyDeviceToDevice, 0);
    cudaMemcpyToSymbolAsync(g_cbuf, c0, (size_t)B_ * H_ * sizeof(float), 0,
                            cudaMemcpyDeviceToDevice, 0);

    float* gx_ptr; cudaGetSymbolAddress((void**)&gx_ptr, g_gx);
    float* hs_ptr; cudaGetSymbolAddress((void**)&hs_ptr, g_hs);

    dim3 grid(8, 128);

    // gx = x @ [W_i|W_f|W_j|W_o] + b
    for (int g = 0; g < 4; g++)
        sgemm128<true><<<grid, 256>>>(x, W[g], bb[g], gx_ptr + g * 1024, G4);

    // persistent recurrence (one kernel, 256 steps inside)
    const int smem_bytes = (4 * 1024 * 8 + 2 * 64 * HPAD) * sizeof(float);
    cudaFuncSetAttribute(lstm_persistent,
                         cudaFuncAttributeMaxDynamicSharedMemorySize, smem_bytes);
    lstm_persistent<<<NBLK, 256, smem_bytes>>>(U[0], U[1], U[2], U[3]);

    // y = hs @ W_y + b_y
    sgemm128<false><<<grid, 256>>>(hs_ptr, Wy, by, y, 1024);
}